// round 16
// baseline (speedup 1.0000x reference)
#include <cuda_runtime.h>
#include <cuda_bf16.h>
#include <cstdint>

// Problem constants (fixed by the reference)
#define NNODES 50000
#define NEDGES 400000
#define CH     256
#define K1     512
#define K2     256

// ---------------------------------------------------------------------------
// Scratch (__device__ globals; no allocations)
// ---------------------------------------------------------------------------
__device__ float    g_h1[(size_t)NNODES * CH];      // GEMM1 out
__device__ float    g_h2[(size_t)NNODES * CH];      // GEMM2 out
__device__ float    g_dinv[NNODES];
__device__ int      g_ideg[NNODES];
__device__ int      g_rowptr[NNODES + 1];
__device__ int      g_cursor[NNODES];
__device__ int      g_esrc[NEDGES];
__device__ int      g_is64;

// bf16 hi/lo pre-converted operands (u32 = packed bf16x2)
__device__ uint32_t g_xhi[(size_t)NNODES * K1 / 2];
__device__ uint32_t g_xlo[(size_t)NNODES * K1 / 2];
__device__ uint32_t g_hrhi[(size_t)NNODES * K2 / 2];
__device__ uint32_t g_hrlo[(size_t)NNODES * K2 / 2];
__device__ uint32_t g_w1hi[CH * K1 / 2];
__device__ uint32_t g_w1lo[CH * K1 / 2];
__device__ uint32_t g_w2hi[CH * K2 / 2];
__device__ uint32_t g_w2lo[CH * K2 / 2];

// ---------------------------------------------------------------------------
// Helpers
// ---------------------------------------------------------------------------
__device__ __forceinline__ uint32_t smem_u32(const void* p) {
    uint32_t a;
    asm("{ .reg .u64 t; cvta.to.shared.u64 t, %1; cvt.u32.u64 %0, t; }" : "=r"(a) : "l"(p));
    return a;
}

#define SW128(o) ((o) ^ (((o) >> 3) & 0x70))

__device__ __forceinline__ void ldsm4(uint32_t* r, uint32_t addr) {
    asm volatile("ldmatrix.sync.aligned.m8n8.x4.shared.b16 {%0,%1,%2,%3}, [%4];"
                 : "=r"(r[0]), "=r"(r[1]), "=r"(r[2]), "=r"(r[3]) : "r"(addr));
}

__device__ __forceinline__ void mma16816(float* c, const uint32_t* a,
                                         uint32_t b0, uint32_t b1) {
    asm volatile(
        "mma.sync.aligned.m16n8k16.row.col.f32.bf16.bf16.f32 "
        "{%0,%1,%2,%3}, {%4,%5,%6,%7}, {%8,%9}, {%0,%1,%2,%3};"
        : "+f"(c[0]), "+f"(c[1]), "+f"(c[2]), "+f"(c[3])
        : "r"(a[0]), "r"(a[1]), "r"(a[2]), "r"(a[3]), "r"(b0), "r"(b1));
}

__device__ __forceinline__ void cpa16(uint32_t dst, const void* src, uint32_t srcsz) {
    asm volatile("cp.async.cg.shared.global [%0], [%1], 16, %2;"
                 :: "r"(dst), "l"(src), "r"(srcsz) : "memory");
}
#define CPA_COMMIT() asm volatile("cp.async.commit_group;" ::: "memory")
#define CPA_WAIT(N)  asm volatile("cp.async.wait_group %0;" :: "n"(N) : "memory")

// Split two fp32 into bf16x2 hi-word + residual bf16x2 lo-word
__device__ __forceinline__ void bsplit2(float x0, float x1, uint32_t& hi, uint32_t& lo) {
    __nv_bfloat16 h0 = __float2bfloat16_rn(x0);
    __nv_bfloat16 h1 = __float2bfloat16_rn(x1);
    float r0 = x0 - __bfloat162float(h0);
    float r1 = x1 - __bfloat162float(h1);
    __nv_bfloat162 hp, lp;
    hp.x = h0; hp.y = h1;
    lp.x = __float2bfloat16_rn(r0); lp.y = __float2bfloat16_rn(r1);
    hi = *reinterpret_cast<uint32_t*>(&hp);
    lo = *reinterpret_cast<uint32_t*>(&lp);
}

// ---------------------------------------------------------------------------
// Combined conversion kernel: x | W1 | W2 -> bf16 hi/lo, 8 floats per item
// ---------------------------------------------------------------------------
#define X_N8  (NNODES * K1 / 8)    // 3,200,000
#define W1_N8 (CH * K1 / 8)        // 16,384
#define W2_N8 (CH * K2 / 8)        // 8,192
#define CONV_TOTAL (X_N8 + W1_N8 + W2_N8)

__global__ void k_conv_all(const float* __restrict__ x,
                           const float* __restrict__ w1,
                           const float* __restrict__ w2)
{
    int idx = blockIdx.x * blockDim.x + threadIdx.x;
    const float* in;
    uint32_t *hi, *lo;
    int li;
    if (idx < X_N8)                    { in = x;  hi = g_xhi;  lo = g_xlo;  li = idx; }
    else if (idx < X_N8 + W1_N8)       { in = w1; hi = g_w1hi; lo = g_w1lo; li = idx - X_N8; }
    else if (idx < CONV_TOTAL)         { in = w2; hi = g_w2hi; lo = g_w2lo; li = idx - X_N8 - W1_N8; }
    else return;
    const float* p = in + (size_t)li * 8;
    float4 a = *(const float4*)p;
    float4 b = *(const float4*)(p + 4);
    uint32_t h0, l0, h1, l1, h2, l2, h3, l3;
    bsplit2(a.x, a.y, h0, l0);  bsplit2(a.z, a.w, h1, l1);
    bsplit2(b.x, b.y, h2, l2);  bsplit2(b.z, b.w, h3, l3);
    *(uint4*)&hi[(size_t)li * 4] = make_uint4(h0, h1, h2, h3);
    *(uint4*)&lo[(size_t)li * 4] = make_uint4(l0, l1, l2, l3);
}

// ---------------------------------------------------------------------------
// bf16 split-3 GEMM, cp.async 3-stage pipeline, full-width N=256 tile.
// C[M,256] = A[M,K] @ B[256,K]^T. CTA tile 128x256, BK=32, 512 threads.
// Row layout (128B, SW128): [hi | lo]. Stage = 48KB; 3 stages = 144KB.
// bb0: row-block offset (for M-chunked GEMM2 pipelining).
// ---------------------------------------------------------------------------
#define GEMM_NTH   512
#define STAGE_SZ   49152
#define GEMM_SMEM  (3 * STAGE_SZ)

__device__ __forceinline__ void load_chunk(
    const uint32_t* __restrict__ Ahi, const uint32_t* __restrict__ Alo,
    const uint32_t* __restrict__ Bhi, const uint32_t* __restrict__ Blo,
    uint32_t buf, int brow, int M, int K, int k0, int t)
{
    const uint32_t bufA = buf;
    const uint32_t bufB = buf + 16384;
#pragma unroll
    for (int it = 0; it < 2; it++) {
        int g = t + it * GEMM_NTH;
        int r = g >> 3, j = g & 7;
        int gr = brow + r;
        const uint32_t* src = (j < 4) ? Ahi : Alo;
        int koff = (j & 3) * 8;
        const void* p = &src[((size_t)gr * K + k0 + koff) >> 1];
        cpa16(bufA + SW128((uint32_t)(r * 128 + j * 16)), p, gr < M ? 16u : 0u);
    }
#pragma unroll
    for (int it = 0; it < 4; it++) {
        int g = t + it * GEMM_NTH;
        int r = g >> 3, j = g & 7;
        const uint32_t* src = (j < 4) ? Bhi : Blo;
        int koff = (j & 3) * 8;
        const void* p = &src[((size_t)r * K + k0 + koff) >> 1];
        cpa16(bufB + SW128((uint32_t)(r * 128 + j * 16)), p, 16u);
    }
}

__device__ __forceinline__ void mma_gemm_body(
    const uint32_t* __restrict__ Ahi, const uint32_t* __restrict__ Alo,
    const uint32_t* __restrict__ Bhi, const uint32_t* __restrict__ Blo,
    float* __restrict__ C, int M, int K, int bb0)
{
    extern __shared__ char dsm_raw[];
    const uint32_t base = smem_u32(dsm_raw);

    const int t    = threadIdx.x;
    const int wid  = t >> 5;
    const int lane = t & 31;
    const int brow = (bb0 + blockIdx.x) * 128;

    const int warp_m = (wid >> 2) * 32;
    const int warp_n = (wid & 3) * 64;

    float acc[2][8][4];
#pragma unroll
    for (int i = 0; i < 2; i++)
#pragma unroll
        for (int j = 0; j < 8; j++)
#pragma unroll
            for (int q = 0; q < 4; q++) acc[i][j][q] = 0.0f;

    const int lr = lane & 15;
    const int kh = lane >> 4;

    const int nch = K >> 5;

    load_chunk(Ahi, Alo, Bhi, Blo, base, brow, M, K, 0, t);
    CPA_COMMIT();
    load_chunk(Ahi, Alo, Bhi, Blo, base + STAGE_SZ, brow, M, K, 32, t);
    CPA_COMMIT();

    for (int c = 0; c < nch; c++) {
        if (c + 2 < nch) {
            uint32_t nxt = base + ((c + 2) % 3) * STAGE_SZ;
            load_chunk(Ahi, Alo, Bhi, Blo, nxt, brow, M, K, (c + 2) << 5, t);
            CPA_COMMIT();
            CPA_WAIT(2);
        } else if (c + 1 < nch) {
            CPA_WAIT(1);
        } else {
            CPA_WAIT(0);
        }
        __syncthreads();

        const uint32_t cur  = base + (c % 3) * STAGE_SZ;
        const uint32_t curA = cur;
        const uint32_t curB = cur + 16384;

#pragma unroll
        for (int s = 0; s < 2; s++) {
            const int jh = s * 2 + kh;
            const int jl = jh + 4;

            uint32_t ah[2][4], bh[4][4];
#pragma unroll
            for (int mi = 0; mi < 2; mi++) {
                int r = warp_m + mi * 16 + lr;
                ldsm4(ah[mi], curA + (uint32_t)(r * 128 + ((jh ^ (r & 7)) << 4)));
            }
#pragma unroll
            for (int nj = 0; nj < 4; nj++) {
                int r = warp_n + nj * 16 + lr;
                ldsm4(bh[nj], curB + (uint32_t)(r * 128 + ((jh ^ (r & 7)) << 4)));
            }
            // hi*hi
#pragma unroll
            for (int mi = 0; mi < 2; mi++)
#pragma unroll
                for (int nj = 0; nj < 4; nj++) {
                    mma16816(acc[mi][nj * 2 + 0], ah[mi], bh[nj][0], bh[nj][2]);
                    mma16816(acc[mi][nj * 2 + 1], ah[mi], bh[nj][1], bh[nj][3]);
                }
            // lo*hi
            {
                uint32_t al[2][4];
#pragma unroll
                for (int mi = 0; mi < 2; mi++) {
                    int r = warp_m + mi * 16 + lr;
                    ldsm4(al[mi], curA + (uint32_t)(r * 128 + ((jl ^ (r & 7)) << 4)));
                }
#pragma unroll
                for (int mi = 0; mi < 2; mi++)
#pragma unroll
                    for (int nj = 0; nj < 4; nj++) {
                        mma16816(acc[mi][nj * 2 + 0], al[mi], bh[nj][0], bh[nj][2]);
                        mma16816(acc[mi][nj * 2 + 1], al[mi], bh[nj][1], bh[nj][3]);
                    }
            }
            // hi*lo
            {
                uint32_t bl[4][4];
#pragma unroll
                for (int nj = 0; nj < 4; nj++) {
                    int r = warp_n + nj * 16 + lr;
                    ldsm4(bl[nj], curB + (uint32_t)(r * 128 + ((jl ^ (r & 7)) << 4)));
                }
#pragma unroll
                for (int mi = 0; mi < 2; mi++)
#pragma unroll
                    for (int nj = 0; nj < 4; nj++) {
                        mma16816(acc[mi][nj * 2 + 0], ah[mi], bl[nj][0], bl[nj][2]);
                        mma16816(acc[mi][nj * 2 + 1], ah[mi], bl[nj][1], bl[nj][3]);
                    }
            }
        }
        __syncthreads();
    }

    // epilogue
    const int qr = lane >> 2;
    const int qc = (lane & 3) * 2;
#pragma unroll
    for (int mi = 0; mi < 2; mi++) {
        int r0 = brow + warp_m + mi * 16 + qr;
#pragma unroll
        for (int n8 = 0; n8 < 8; n8++) {
            int col = warp_n + n8 * 8 + qc;
            if (r0 < M) {
                float2 v = make_float2(acc[mi][n8][0], acc[mi][n8][1]);
                *(float2*)&C[(size_t)r0 * 256 + col] = v;
            }
            if (r0 + 8 < M) {
                float2 v = make_float2(acc[mi][n8][2], acc[mi][n8][3]);
                *(float2*)&C[(size_t)(r0 + 8) * 256 + col] = v;
            }
        }
    }
}

__global__ void __launch_bounds__(GEMM_NTH, 1)
k_mmagemm1() { mma_gemm_body(g_xhi, g_xlo, g_w1hi, g_w1lo, g_h1, NNODES, K1, 0); }
__global__ void __launch_bounds__(GEMM_NTH, 1)
k_mmagemm2(int bb0) {
    mma_gemm_body(g_hrhi, g_hrlo, g_w2hi, g_w2lo, g_h2, NNODES, K2, bb0);
}

// ---------------------------------------------------------------------------
// edge_index access (int64 per spec; tolerate int32 via runtime detection)
// ---------------------------------------------------------------------------
__device__ __forceinline__ int edge_idx(const void* ei, int half, int e) {
    if (g_is64) return (int)((const long long*)ei)[(size_t)half * NEDGES + e];
    return ((const int*)ei)[(size_t)half * NEDGES + e];
}

// ---------------------------------------------------------------------------
// CSR build: zero+detect -> count -> scan(+dinv) -> fill
// ---------------------------------------------------------------------------
__global__ void k_zero_detect(const long long* __restrict__ ei) {
    int i = blockIdx.x * blockDim.x + threadIdx.x;
    if (i < NNODES) g_ideg[i] = 0;
    if (blockIdx.x == 0 && threadIdx.x == 0) {
        int is64 = 1;
        for (int q = 0; q < 256; q++) {
            long long v = ei[q];
            if (v < 0 || v >= NNODES) { is64 = 0; break; }
        }
        g_is64 = is64;
    }
}

__global__ void k_count(const void* __restrict__ ei) {
    int e = blockIdx.x * blockDim.x + threadIdx.x;
    if (e < NEDGES) atomicAdd(&g_ideg[edge_idx(ei, 1, e)], 1);
}

#define SCAN_T 1024
#define SCAN_C ((NNODES + SCAN_T - 1) / SCAN_T)
__global__ void __launch_bounds__(SCAN_T)
k_scan() {
    __shared__ int part[SCAN_T];
    const int t = threadIdx.x;
    const int start = t * SCAN_C;
    const int end   = min(start + SCAN_C, NNODES);
    int s = 0;
    for (int i = start; i < end; i++) s += g_ideg[i];
    part[t] = s;
    __syncthreads();
    for (int off = 1; off < SCAN_T; off <<= 1) {
        int v = (t >= off) ? part[t - off] : 0;
        __syncthreads();
        part[t] += v;
        __syncthreads();
    }
    int run = part[t] - s;
    for (int i = start; i < end; i++) {
        int d = g_ideg[i];
        g_rowptr[i] = run;
        g_cursor[i] = run;
        g_dinv[i]   = rsqrtf(1.0f + (float)d);
        run += d;
    }
    if (t == SCAN_T - 1) g_rowptr[NNODES] = part[SCAN_T - 1];
}

__global__ void k_fill(const void* __restrict__ ei) {
    int e = blockIdx.x * blockDim.x + threadIdx.x;
    if (e >= NEDGES) return;
    int s = edge_idx(ei, 0, e);
    int d = edge_idx(ei, 1, e);
    int pos = atomicAdd(&g_cursor[d], 1);
    g_esrc[pos] = s;
}

// ---------------------------------------------------------------------------
// Gather aggregation: one warp per node.
// ---------------------------------------------------------------------------
__device__ __forceinline__ void gather_acc(
    const float* __restrict__ h, const float* __restrict__ bias,
    int node, int lane, float4& a0, float4& a1)
{
    const float dv = g_dinv[node];
    const float* hd = h + (size_t)node * CH;
    a0 = *(const float4*)&hd[lane * 4];
    a1 = *(const float4*)&hd[128 + lane * 4];
    const float sv = dv * dv;
    a0.x *= sv; a0.y *= sv; a0.z *= sv; a0.w *= sv;
    a1.x *= sv; a1.y *= sv; a1.z *= sv; a1.w *= sv;

    const int p0 = g_rowptr[node];
    const int p1 = g_rowptr[node + 1];
    for (int p = p0; p < p1; p++) {
        int s = g_esrc[p];
        float w = g_dinv[s] * dv;
        const float* hs = h + (size_t)s * CH;
        float4 v0 = *(const float4*)&hs[lane * 4];
        float4 v1 = *(const float4*)&hs[128 + lane * 4];
        a0.x = fmaf(v0.x, w, a0.x); a0.y = fmaf(v0.y, w, a0.y);
        a0.z = fmaf(v0.z, w, a0.z); a0.w = fmaf(v0.w, w, a0.w);
        a1.x = fmaf(v1.x, w, a1.x); a1.y = fmaf(v1.y, w, a1.y);
        a1.z = fmaf(v1.z, w, a1.z); a1.w = fmaf(v1.w, w, a1.w);
    }

    const float4 b0 = *(const float4*)&bias[lane * 4];
    const float4 b1 = *(const float4*)&bias[128 + lane * 4];
    a0.x += b0.x; a0.y += b0.y; a0.z += b0.z; a0.w += b0.w;
    a1.x += b1.x; a1.y += b1.y; a1.z += b1.z; a1.w += b1.w;
}

// layer 1 (node-range): relu then emit bf16 hi/lo split directly (GEMM2 input)
__global__ void __launch_bounds__(256)
k_gather1(const float* __restrict__ b1, int node0, int ncount)
{
    const int wid  = threadIdx.x >> 5;
    const int lane = threadIdx.x & 31;
    const int node = node0 + blockIdx.x * 8 + wid;
    if (node >= node0 + ncount) return;
    float4 a0, a1;
    gather_acc(g_h1, b1, node, lane, a0, a1);
    a0.x = fmaxf(a0.x, 0.f); a0.y = fmaxf(a0.y, 0.f);
    a0.z = fmaxf(a0.z, 0.f); a0.w = fmaxf(a0.w, 0.f);
    a1.x = fmaxf(a1.x, 0.f); a1.y = fmaxf(a1.y, 0.f);
    a1.z = fmaxf(a1.z, 0.f); a1.w = fmaxf(a1.w, 0.f);

    uint32_t h0, l0, h1, l1;
    size_t bix = (size_t)node * 128 + lane * 2;
    bsplit2(a0.x, a0.y, h0, l0); bsplit2(a0.z, a0.w, h1, l1);
    *(uint2*)&g_hrhi[bix] = make_uint2(h0, h1);
    *(uint2*)&g_hrlo[bix] = make_uint2(l0, l1);
    bsplit2(a1.x, a1.y, h0, l0); bsplit2(a1.z, a1.w, h1, l1);
    *(uint2*)&g_hrhi[bix + 64] = make_uint2(h0, h1);
    *(uint2*)&g_hrlo[bix + 64] = make_uint2(l0, l1);
}

// layer 2: plain output
__global__ void __launch_bounds__(256)
k_gather2(const float* __restrict__ b2, float* __restrict__ out)
{
    const int wid  = threadIdx.x >> 5;
    const int lane = threadIdx.x & 31;
    const int node = blockIdx.x * 8 + wid;
    if (node >= NNODES) return;
    float4 a0, a1;
    gather_acc(g_h2, b2, node, lane, a0, a1);
    float* od = out + (size_t)node * CH;
    *(float4*)&od[lane * 4]       = a0;
    *(float4*)&od[128 + lane * 4] = a1;
}

// ---------------------------------------------------------------------------
// Launch — R12 topology (1 extra stream) + 2-chunk gather1->GEMM2 pipeline.
// GEMM2 chunk0 = row-blocks [0,148) (one full wave), chunk1 = [148,391).
// ---------------------------------------------------------------------------
extern "C" void kernel_launch(void* const* d_in, const int* in_sizes, int n_in,
                              void* d_out, int out_size)
{
    const float* x   = (const float*)d_in[0];
    const void*  ei  = d_in[1];
    const float* W1  = (const float*)d_in[2];
    const float* b1  = (const float*)d_in[3];
    const float* W2  = (const float*)d_in[4];
    const float* b2  = (const float*)d_in[5];
    float*       out = (float*)d_out;

    static cudaStream_t s2 = nullptr;
    static cudaEvent_t  e0, eG1, eGa0, eGa1, eG2;
    if (!s2) {
        cudaFuncSetAttribute(k_mmagemm1, cudaFuncAttributeMaxDynamicSharedMemorySize, GEMM_SMEM);
        cudaFuncSetAttribute(k_mmagemm2, cudaFuncAttributeMaxDynamicSharedMemorySize, GEMM_SMEM);
        cudaStreamCreateWithFlags(&s2, cudaStreamNonBlocking);
        cudaEventCreateWithFlags(&e0,  cudaEventDisableTiming);
        cudaEventCreateWithFlags(&eG1, cudaEventDisableTiming);
        cudaEventCreateWithFlags(&eGa0, cudaEventDisableTiming);
        cudaEventCreateWithFlags(&eGa1, cudaEventDisableTiming);
        cudaEventCreateWithFlags(&eG2, cudaEventDisableTiming);
    }

    const int NTH = 256;
    const int nblk_nodes = (NNODES + NTH - 1) / NTH;
    const int nblk_edges = (NEDGES + NTH - 1) / NTH;
    const int nblk_conv  = (CONV_TOTAL + NTH - 1) / NTH;
    const int gemm_grid  = (NNODES + 127) / 128;       // 391

    // gather1 / GEMM2 chunk geometry
    const int g2blk0  = 148;                  // row-blocks in chunk0 (one wave)
    const int g2blk1  = gemm_grid - g2blk0;   // 243
    const int nodes0  = g2blk0 * 128;         // 18944
    const int ncnt1   = NNODES - nodes0;      // 31056

    // fork: CSR chain on s2 (consumed by gather1; finishes well before needed)
    cudaEventRecord(e0, 0);
    cudaStreamWaitEvent(s2, e0, 0);
    k_zero_detect<<<nblk_nodes, NTH, 0, s2>>>((const long long*)ei);
    k_count<<<nblk_edges, NTH, 0, s2>>>(ei);
    k_scan<<<1, SCAN_T, 0, s2>>>();
    k_fill<<<nblk_edges, NTH, 0, s2>>>(ei);
    // (no event needed: s2's next work is GEMM2, ordered after CSR in-stream;
    //  but gather1 on s0 needs CSR -> record an event on s2 here)
    cudaEventRecord(eG1, s2);   // reuse as "CSR done"

    // main: conv + GEMM1
    k_conv_all<<<nblk_conv, NTH>>>(x, W1, W2);
    k_mmagemm1<<<gemm_grid, GEMM_NTH, GEMM_SMEM>>>();

    // gather1 chunk 0 (needs CSR + all of h1)
    cudaStreamWaitEvent(0, eG1, 0);
    k_gather1<<<(nodes0 + 7) / 8, NTH>>>(b1, 0, nodes0);
    cudaEventRecord(eGa0, 0);
    // gather1 chunk 1
    k_gather1<<<(ncnt1 + 7) / 8, NTH>>>(b1, nodes0, ncnt1);
    cudaEventRecord(eGa1, 0);

    // s2: GEMM2 chunks (chunk i gated on gather1 chunk i)
    cudaStreamWaitEvent(s2, eGa0, 0);
    k_mmagemm2<<<g2blk0, GEMM_NTH, GEMM_SMEM, s2>>>(0);
    cudaStreamWaitEvent(s2, eGa1, 0);
    k_mmagemm2<<<g2blk1, GEMM_NTH, GEMM_SMEM, s2>>>(g2blk0);
    cudaEventRecord(eG2, s2);

    // s0: gather2 after all GEMM2
    cudaStreamWaitEvent(0, eG2, 0);
    k_gather2<<<(NNODES + 7) / 8, NTH>>>(b2, out);
}

// round 17
// speedup vs baseline: 1.2939x; 1.2939x over previous
#include <cuda_runtime.h>
#include <cuda_bf16.h>
#include <cstdint>

// Problem constants (fixed by the reference)
#define NNODES 50000
#define NEDGES 400000
#define CH     256
#define K1     512
#define K2     256

// ---------------------------------------------------------------------------
// Scratch (__device__ globals; no allocations)
// ---------------------------------------------------------------------------
__device__ float    g_h1[(size_t)NNODES * CH];      // GEMM1 out
__device__ float    g_h2[(size_t)NNODES * CH];      // GEMM2 out
__device__ float    g_dinv[NNODES];
__device__ int      g_ideg[NNODES];
__device__ int      g_rowptr[NNODES + 1];
__device__ int      g_cursor[NNODES];
__device__ int      g_esrc[NEDGES];
__device__ int      g_is64;

// bf16 hi/lo pre-converted operands (u32 = packed bf16x2)
__device__ uint32_t g_xhi[(size_t)NNODES * K1 / 2];
__device__ uint32_t g_xlo[(size_t)NNODES * K1 / 2];
__device__ uint32_t g_hrhi[(size_t)NNODES * K2 / 2];
__device__ uint32_t g_hrlo[(size_t)NNODES * K2 / 2];
__device__ uint32_t g_w1hi[CH * K1 / 2];
__device__ uint32_t g_w1lo[CH * K1 / 2];
__device__ uint32_t g_w2hi[CH * K2 / 2];
__device__ uint32_t g_w2lo[CH * K2 / 2];

// ---------------------------------------------------------------------------
// Helpers
// ---------------------------------------------------------------------------
__device__ __forceinline__ uint32_t smem_u32(const void* p) {
    uint32_t a;
    asm("{ .reg .u64 t; cvta.to.shared.u64 t, %1; cvt.u32.u64 %0, t; }" : "=r"(a) : "l"(p));
    return a;
}

#define SW128(o) ((o) ^ (((o) >> 3) & 0x70))

__device__ __forceinline__ void ldsm4(uint32_t* r, uint32_t addr) {
    asm volatile("ldmatrix.sync.aligned.m8n8.x4.shared.b16 {%0,%1,%2,%3}, [%4];"
                 : "=r"(r[0]), "=r"(r[1]), "=r"(r[2]), "=r"(r[3]) : "r"(addr));
}

__device__ __forceinline__ void mma16816(float* c, const uint32_t* a,
                                         uint32_t b0, uint32_t b1) {
    asm volatile(
        "mma.sync.aligned.m16n8k16.row.col.f32.bf16.bf16.f32 "
        "{%0,%1,%2,%3}, {%4,%5,%6,%7}, {%8,%9}, {%0,%1,%2,%3};"
        : "+f"(c[0]), "+f"(c[1]), "+f"(c[2]), "+f"(c[3])
        : "r"(a[0]), "r"(a[1]), "r"(a[2]), "r"(a[3]), "r"(b0), "r"(b1));
}

__device__ __forceinline__ void cpa16(uint32_t dst, const void* src, uint32_t srcsz) {
    asm volatile("cp.async.cg.shared.global [%0], [%1], 16, %2;"
                 :: "r"(dst), "l"(src), "r"(srcsz) : "memory");
}
#define CPA_COMMIT() asm volatile("cp.async.commit_group;" ::: "memory")
#define CPA_WAIT(N)  asm volatile("cp.async.wait_group %0;" :: "n"(N) : "memory")

// Split two fp32 into bf16x2 hi-word + residual bf16x2 lo-word
__device__ __forceinline__ void bsplit2(float x0, float x1, uint32_t& hi, uint32_t& lo) {
    __nv_bfloat16 h0 = __float2bfloat16_rn(x0);
    __nv_bfloat16 h1 = __float2bfloat16_rn(x1);
    float r0 = x0 - __bfloat162float(h0);
    float r1 = x1 - __bfloat162float(h1);
    __nv_bfloat162 hp, lp;
    hp.x = h0; hp.y = h1;
    lp.x = __float2bfloat16_rn(r0); lp.y = __float2bfloat16_rn(r1);
    hi = *reinterpret_cast<uint32_t*>(&hp);
    lo = *reinterpret_cast<uint32_t*>(&lp);
}

// ---------------------------------------------------------------------------
// Combined conversion kernel: x | W1 | W2 -> bf16 hi/lo, 8 floats per item
// ---------------------------------------------------------------------------
#define X_N8  (NNODES * K1 / 8)    // 3,200,000
#define W1_N8 (CH * K1 / 8)        // 16,384
#define W2_N8 (CH * K2 / 8)        // 8,192
#define CONV_TOTAL (X_N8 + W1_N8 + W2_N8)

__global__ void k_conv_all(const float* __restrict__ x,
                           const float* __restrict__ w1,
                           const float* __restrict__ w2)
{
    int idx = blockIdx.x * blockDim.x + threadIdx.x;
    const float* in;
    uint32_t *hi, *lo;
    int li;
    if (idx < X_N8)                    { in = x;  hi = g_xhi;  lo = g_xlo;  li = idx; }
    else if (idx < X_N8 + W1_N8)       { in = w1; hi = g_w1hi; lo = g_w1lo; li = idx - X_N8; }
    else if (idx < CONV_TOTAL)         { in = w2; hi = g_w2hi; lo = g_w2lo; li = idx - X_N8 - W1_N8; }
    else return;
    const float* p = in + (size_t)li * 8;
    float4 a = *(const float4*)p;
    float4 b = *(const float4*)(p + 4);
    uint32_t h0, l0, h1, l1, h2, l2, h3, l3;
    bsplit2(a.x, a.y, h0, l0);  bsplit2(a.z, a.w, h1, l1);
    bsplit2(b.x, b.y, h2, l2);  bsplit2(b.z, b.w, h3, l3);
    *(uint4*)&hi[(size_t)li * 4] = make_uint4(h0, h1, h2, h3);
    *(uint4*)&lo[(size_t)li * 4] = make_uint4(l0, l1, l2, l3);
}

// ---------------------------------------------------------------------------
// bf16 split-3 GEMM, cp.async 3-stage pipeline, full-width N=256 tile.
// C[M,256] = A[M,K] @ B[256,K]^T. CTA tile 128x256, BK=32, 512 threads.
// Row layout (128B, SW128): [hi: 32 bf16 = 64B | lo: 32 bf16 = 64B]
// Stage = A(16KB) + B(32KB) = 48KB; 3 stages = 144KB. 16 warps: 4m x 4n.
// ---------------------------------------------------------------------------
#define GEMM_NTH   512
#define STAGE_SZ   49152
#define GEMM_SMEM  (3 * STAGE_SZ)

__device__ __forceinline__ void load_chunk(
    const uint32_t* __restrict__ Ahi, const uint32_t* __restrict__ Alo,
    const uint32_t* __restrict__ Bhi, const uint32_t* __restrict__ Blo,
    uint32_t buf, int brow, int M, int K, int k0, int t)
{
    const uint32_t bufA = buf;
    const uint32_t bufB = buf + 16384;
    // A: 128 rows x 8 groups = 1024 items, 2 per thread
#pragma unroll
    for (int it = 0; it < 2; it++) {
        int g = t + it * GEMM_NTH;
        int r = g >> 3, j = g & 7;
        int gr = brow + r;
        const uint32_t* src = (j < 4) ? Ahi : Alo;
        int koff = (j & 3) * 8;
        const void* p = &src[((size_t)gr * K + k0 + koff) >> 1];
        cpa16(bufA + SW128((uint32_t)(r * 128 + j * 16)), p, gr < M ? 16u : 0u);
    }
    // B: 256 rows x 8 groups = 2048 items, 4 per thread
#pragma unroll
    for (int it = 0; it < 4; it++) {
        int g = t + it * GEMM_NTH;
        int r = g >> 3, j = g & 7;
        const uint32_t* src = (j < 4) ? Bhi : Blo;
        int koff = (j & 3) * 8;
        const void* p = &src[((size_t)r * K + k0 + koff) >> 1];
        cpa16(bufB + SW128((uint32_t)(r * 128 + j * 16)), p, 16u);
    }
}

__device__ __forceinline__ void mma_gemm_body(
    const uint32_t* __restrict__ Ahi, const uint32_t* __restrict__ Alo,
    const uint32_t* __restrict__ Bhi, const uint32_t* __restrict__ Blo,
    float* __restrict__ C, int M, int K)
{
    extern __shared__ char dsm_raw[];
    const uint32_t base = smem_u32(dsm_raw);

    const int t    = threadIdx.x;
    const int wid  = t >> 5;
    const int lane = t & 31;
    const int brow = blockIdx.x * 128;

    const int warp_m = (wid >> 2) * 32;
    const int warp_n = (wid & 3) * 64;

    float acc[2][8][4];
#pragma unroll
    for (int i = 0; i < 2; i++)
#pragma unroll
        for (int j = 0; j < 8; j++)
#pragma unroll
            for (int q = 0; q < 4; q++) acc[i][j][q] = 0.0f;

    const int lr = lane & 15;
    const int kh = lane >> 4;

    const int nch = K >> 5;

    load_chunk(Ahi, Alo, Bhi, Blo, base, brow, M, K, 0, t);
    CPA_COMMIT();
    load_chunk(Ahi, Alo, Bhi, Blo, base + STAGE_SZ, brow, M, K, 32, t);
    CPA_COMMIT();

    for (int c = 0; c < nch; c++) {
        if (c + 2 < nch) {
            uint32_t nxt = base + ((c + 2) % 3) * STAGE_SZ;
            load_chunk(Ahi, Alo, Bhi, Blo, nxt, brow, M, K, (c + 2) << 5, t);
            CPA_COMMIT();
            CPA_WAIT(2);
        } else if (c + 1 < nch) {
            CPA_WAIT(1);
        } else {
            CPA_WAIT(0);
        }
        __syncthreads();

        const uint32_t cur  = base + (c % 3) * STAGE_SZ;
        const uint32_t curA = cur;
        const uint32_t curB = cur + 16384;

#pragma unroll
        for (int s = 0; s < 2; s++) {
            const int jh = s * 2 + kh;
            const int jl = jh + 4;

            uint32_t ah[2][4], bh[4][4];
#pragma unroll
            for (int mi = 0; mi < 2; mi++) {
                int r = warp_m + mi * 16 + lr;
                ldsm4(ah[mi], curA + (uint32_t)(r * 128 + ((jh ^ (r & 7)) << 4)));
            }
#pragma unroll
            for (int nj = 0; nj < 4; nj++) {
                int r = warp_n + nj * 16 + lr;
                ldsm4(bh[nj], curB + (uint32_t)(r * 128 + ((jh ^ (r & 7)) << 4)));
            }
            // hi*hi
#pragma unroll
            for (int mi = 0; mi < 2; mi++)
#pragma unroll
                for (int nj = 0; nj < 4; nj++) {
                    mma16816(acc[mi][nj * 2 + 0], ah[mi], bh[nj][0], bh[nj][2]);
                    mma16816(acc[mi][nj * 2 + 1], ah[mi], bh[nj][1], bh[nj][3]);
                }
            // lo*hi
            {
                uint32_t al[2][4];
#pragma unroll
                for (int mi = 0; mi < 2; mi++) {
                    int r = warp_m + mi * 16 + lr;
                    ldsm4(al[mi], curA + (uint32_t)(r * 128 + ((jl ^ (r & 7)) << 4)));
                }
#pragma unroll
                for (int mi = 0; mi < 2; mi++)
#pragma unroll
                    for (int nj = 0; nj < 4; nj++) {
                        mma16816(acc[mi][nj * 2 + 0], al[mi], bh[nj][0], bh[nj][2]);
                        mma16816(acc[mi][nj * 2 + 1], al[mi], bh[nj][1], bh[nj][3]);
                    }
            }
            // hi*lo
            {
                uint32_t bl[4][4];
#pragma unroll
                for (int nj = 0; nj < 4; nj++) {
                    int r = warp_n + nj * 16 + lr;
                    ldsm4(bl[nj], curB + (uint32_t)(r * 128 + ((jl ^ (r & 7)) << 4)));
                }
#pragma unroll
                for (int mi = 0; mi < 2; mi++)
#pragma unroll
                    for (int nj = 0; nj < 4; nj++) {
                        mma16816(acc[mi][nj * 2 + 0], ah[mi], bl[nj][0], bl[nj][2]);
                        mma16816(acc[mi][nj * 2 + 1], ah[mi], bl[nj][1], bl[nj][3]);
                    }
            }
        }
        __syncthreads();
    }

    // epilogue
    const int qr = lane >> 2;
    const int qc = (lane & 3) * 2;
#pragma unroll
    for (int mi = 0; mi < 2; mi++) {
        int r0 = brow + warp_m + mi * 16 + qr;
#pragma unroll
        for (int n8 = 0; n8 < 8; n8++) {
            int col = warp_n + n8 * 8 + qc;
            if (r0 < M) {
                float2 v = make_float2(acc[mi][n8][0], acc[mi][n8][1]);
                *(float2*)&C[(size_t)r0 * 256 + col] = v;
            }
            if (r0 + 8 < M) {
                float2 v = make_float2(acc[mi][n8][2], acc[mi][n8][3]);
                *(float2*)&C[(size_t)(r0 + 8) * 256 + col] = v;
            }
        }
    }
}

__global__ void __launch_bounds__(GEMM_NTH, 1)
k_mmagemm1() { mma_gemm_body(g_xhi, g_xlo, g_w1hi, g_w1lo, g_h1, NNODES, K1); }
__global__ void __launch_bounds__(GEMM_NTH, 1)
k_mmagemm2() { mma_gemm_body(g_hrhi, g_hrlo, g_w2hi, g_w2lo, g_h2, NNODES, K2); }

// ---------------------------------------------------------------------------
// edge_index access (int64 per spec; tolerate int32 via runtime detection)
// ---------------------------------------------------------------------------
__device__ __forceinline__ int edge_idx(const void* ei, int half, int e) {
    if (g_is64) return (int)((const long long*)ei)[(size_t)half * NEDGES + e];
    return ((const int*)ei)[(size_t)half * NEDGES + e];
}

// ---------------------------------------------------------------------------
// CSR build: zero+detect -> count -> scan(+dinv) -> fill
// ---------------------------------------------------------------------------
__global__ void k_zero_detect(const long long* __restrict__ ei) {
    int i = blockIdx.x * blockDim.x + threadIdx.x;
    if (i < NNODES) g_ideg[i] = 0;
    if (blockIdx.x == 0 && threadIdx.x == 0) {
        int is64 = 1;
        for (int q = 0; q < 256; q++) {
            long long v = ei[q];
            if (v < 0 || v >= NNODES) { is64 = 0; break; }
        }
        g_is64 = is64;
    }
}

__global__ void k_count(const void* __restrict__ ei) {
    int e = blockIdx.x * blockDim.x + threadIdx.x;
    if (e < NEDGES) atomicAdd(&g_ideg[edge_idx(ei, 1, e)], 1);
}

#define SCAN_T 1024
#define SCAN_C ((NNODES + SCAN_T - 1) / SCAN_T)
__global__ void __launch_bounds__(SCAN_T)
k_scan() {
    __shared__ int part[SCAN_T];
    const int t = threadIdx.x;
    const int start = t * SCAN_C;
    const int end   = min(start + SCAN_C, NNODES);
    int s = 0;
    for (int i = start; i < end; i++) s += g_ideg[i];
    part[t] = s;
    __syncthreads();
    for (int off = 1; off < SCAN_T; off <<= 1) {
        int v = (t >= off) ? part[t - off] : 0;
        __syncthreads();
        part[t] += v;
        __syncthreads();
    }
    int run = part[t] - s;
    for (int i = start; i < end; i++) {
        int d = g_ideg[i];
        g_rowptr[i] = run;
        g_cursor[i] = run;
        g_dinv[i]   = rsqrtf(1.0f + (float)d);
        run += d;
    }
    if (t == SCAN_T - 1) g_rowptr[NNODES] = part[SCAN_T - 1];
}

__global__ void k_fill(const void* __restrict__ ei) {
    int e = blockIdx.x * blockDim.x + threadIdx.x;
    if (e >= NEDGES) return;
    int s = edge_idx(ei, 0, e);
    int d = edge_idx(ei, 1, e);
    int pos = atomicAdd(&g_cursor[d], 1);
    g_esrc[pos] = s;
}

// ---------------------------------------------------------------------------
// Gather aggregation: one warp per node.
// ---------------------------------------------------------------------------
__device__ __forceinline__ void gather_acc(
    const float* __restrict__ h, const float* __restrict__ bias,
    int node, int lane, float4& a0, float4& a1)
{
    const float dv = g_dinv[node];
    const float* hd = h + (size_t)node * CH;
    a0 = *(const float4*)&hd[lane * 4];
    a1 = *(const float4*)&hd[128 + lane * 4];
    const float sv = dv * dv;
    a0.x *= sv; a0.y *= sv; a0.z *= sv; a0.w *= sv;
    a1.x *= sv; a1.y *= sv; a1.z *= sv; a1.w *= sv;

    const int p0 = g_rowptr[node];
    const int p1 = g_rowptr[node + 1];
    for (int p = p0; p < p1; p++) {
        int s = g_esrc[p];
        float w = g_dinv[s] * dv;
        const float* hs = h + (size_t)s * CH;
        float4 v0 = *(const float4*)&hs[lane * 4];
        float4 v1 = *(const float4*)&hs[128 + lane * 4];
        a0.x = fmaf(v0.x, w, a0.x); a0.y = fmaf(v0.y, w, a0.y);
        a0.z = fmaf(v0.z, w, a0.z); a0.w = fmaf(v0.w, w, a0.w);
        a1.x = fmaf(v1.x, w, a1.x); a1.y = fmaf(v1.y, w, a1.y);
        a1.z = fmaf(v1.z, w, a1.z); a1.w = fmaf(v1.w, w, a1.w);
    }

    const float4 b0 = *(const float4*)&bias[lane * 4];
    const float4 b1 = *(const float4*)&bias[128 + lane * 4];
    a0.x += b0.x; a0.y += b0.y; a0.z += b0.z; a0.w += b0.w;
    a1.x += b1.x; a1.y += b1.y; a1.z += b1.z; a1.w += b1.w;
}

// layer 1: relu then emit bf16 hi/lo split directly (GEMM2 input)
__global__ void __launch_bounds__(256)
k_gather1(const float* __restrict__ b1)
{
    const int wid  = threadIdx.x >> 5;
    const int lane = threadIdx.x & 31;
    const int node = blockIdx.x * 8 + wid;
    if (node >= NNODES) return;
    float4 a0, a1;
    gather_acc(g_h1, b1, node, lane, a0, a1);
    a0.x = fmaxf(a0.x, 0.f); a0.y = fmaxf(a0.y, 0.f);
    a0.z = fmaxf(a0.z, 0.f); a0.w = fmaxf(a0.w, 0.f);
    a1.x = fmaxf(a1.x, 0.f); a1.y = fmaxf(a1.y, 0.f);
    a1.z = fmaxf(a1.z, 0.f); a1.w = fmaxf(a1.w, 0.f);

    uint32_t h0, l0, h1, l1;
    size_t bix = (size_t)node * 128 + lane * 2;
    bsplit2(a0.x, a0.y, h0, l0); bsplit2(a0.z, a0.w, h1, l1);
    *(uint2*)&g_hrhi[bix] = make_uint2(h0, h1);
    *(uint2*)&g_hrlo[bix] = make_uint2(l0, l1);
    bsplit2(a1.x, a1.y, h0, l0); bsplit2(a1.z, a1.w, h1, l1);
    *(uint2*)&g_hrhi[bix + 64] = make_uint2(h0, h1);
    *(uint2*)&g_hrlo[bix + 64] = make_uint2(l0, l1);
}

// layer 2: plain output
__global__ void __launch_bounds__(256)
k_gather2(const float* __restrict__ b2, float* __restrict__ out)
{
    const int wid  = threadIdx.x >> 5;
    const int lane = threadIdx.x & 31;
    const int node = blockIdx.x * 8 + wid;
    if (node >= NNODES) return;
    float4 a0, a1;
    gather_acc(g_h2, b2, node, lane, a0, a1);
    float* od = out + (size_t)node * CH;
    *(float4*)&od[lane * 4]       = a0;
    *(float4*)&od[128 + lane * 4] = a1;
}

// ---------------------------------------------------------------------------
// Launch
// ---------------------------------------------------------------------------
extern "C" void kernel_launch(void* const* d_in, const int* in_sizes, int n_in,
                              void* d_out, int out_size)
{
    const float* x   = (const float*)d_in[0];
    const void*  ei  = d_in[1];
    const float* W1  = (const float*)d_in[2];
    const float* b1  = (const float*)d_in[3];
    const float* W2  = (const float*)d_in[4];
    const float* b2  = (const float*)d_in[5];
    float*       out = (float*)d_out;

    static cudaStream_t s2 = nullptr;
    static cudaEvent_t  e0 = nullptr, e1 = nullptr;
    if (!s2) {
        cudaFuncSetAttribute(k_mmagemm1, cudaFuncAttributeMaxDynamicSharedMemorySize, GEMM_SMEM);
        cudaFuncSetAttribute(k_mmagemm2, cudaFuncAttributeMaxDynamicSharedMemorySize, GEMM_SMEM);
        cudaStreamCreateWithFlags(&s2, cudaStreamNonBlocking);
        cudaEventCreateWithFlags(&e0, cudaEventDisableTiming);
        cudaEventCreateWithFlags(&e1, cudaEventDisableTiming);
    }

    const int NTH = 256;
    const int nblk_nodes  = (NNODES + NTH - 1) / NTH;
    const int nblk_edges  = (NEDGES + NTH - 1) / NTH;
    const int nblk_gather = (NNODES + 7) / 8;
    const int nblk_conv   = (CONV_TOTAL + NTH - 1) / NTH;

    const int gemm_grid = (NNODES + 127) / 128;   // 391

    // fork: CSR chain on s2 (only gather1 depends on it)
    cudaEventRecord(e0, 0);
    cudaStreamWaitEvent(s2, e0, 0);
    k_zero_detect<<<nblk_nodes, NTH, 0, s2>>>((const long long*)ei);
    k_count<<<nblk_edges, NTH, 0, s2>>>(ei);
    k_scan<<<1, SCAN_T, 0, s2>>>();
    k_fill<<<nblk_edges, NTH, 0, s2>>>(ei);
    cudaEventRecord(e1, s2);

    // main: one conversion kernel (x + W1 + W2), then GEMM1
    k_conv_all<<<nblk_conv, NTH>>>(x, W1, W2);
    k_mmagemm1<<<gemm_grid, GEMM_NTH, GEMM_SMEM>>>();

    // join: gather1 needs CSR + dinv
    cudaStreamWaitEvent(0, e1, 0);
    k_gather1<<<nblk_gather, NTH>>>(b1);

    // layer 2
    k_mmagemm2<<<gemm_grid, GEMM_NTH, GEMM_SMEM>>>();
    k_gather2<<<nblk_gather, NTH>>>(b2, out);
}